// round 10
// baseline (speedup 1.0000x reference)
#include <cuda_runtime.h>
#include <cuda_fp16.h>
#include <cstdint>
#include <cstddef>

constexpr int Kn = 1024, Cc = 128, Dd = 6272, FFNn = 1024, CPG = 32, DYN = 36864, Mb = 64;

// ---------------- fp32 scratch ----------------
__device__ __align__(128) float g_v   [(size_t)Kn * Dd];
__device__ __align__(128) float g_bufA[(size_t)Kn * Dd];
__device__ __align__(128) float g_x   [(size_t)Kn * Dd];
__device__ __align__(128) float g_flat[(size_t)Kn * Dd];
__device__ __align__(128) float g_gap [(size_t)Kn * Cc];
__device__ __align__(128) float g_dyn [(size_t)Kn * DYN];
__device__ __align__(128) float g_h   [(size_t)Kn * FFNn];
__device__ __align__(128) float g_part[(size_t)2 * Kn * Dd];   // split-K partials

// ---------------- PTX helpers ----------------
__device__ __forceinline__ void mma_h(float* c, const uint32_t* a, const uint32_t* b) {
    asm volatile(
        "mma.sync.aligned.m16n8k16.row.col.f32.f16.f16.f32 "
        "{%0,%1,%2,%3}, {%4,%5,%6,%7}, {%8,%9}, {%0,%1,%2,%3};"
        : "+f"(c[0]), "+f"(c[1]), "+f"(c[2]), "+f"(c[3])
        : "r"(a[0]), "r"(a[1]), "r"(a[2]), "r"(a[3]), "r"(b[0]), "r"(b[1]));
}
__device__ __forceinline__ uint32_t pk(float x, float y) {
    __half2 h = __floats2half2_rn(x, y);   // low = x (even k), high = y (odd k)
    return *reinterpret_cast<uint32_t*>(&h);
}

// ============================================================
// fp16 tensor-core GEMM: C[M,N] = A[M,K]·B[N,K]^T (+bias/res/relu if Z==1)
// Block 256x128, 8 warps (64x64 each), k-tile 16 (one m16n8k16 in k).
// Loader: LDG.128 fp32 -> cvt f16x2 -> STS.64, 2-stage double buffer.
// smem row pitch 24 halves (48B) -> conflict-free fragment LDS.
// gridDim.z = Z-way split-K; Z>1 writes raw fp32 partials to `part`.
// ============================================================
constexpr int HPITCH = 24;                 // halves per 16-half k row
constexpr int AH = 256 * HPITCH;           // A stage halves
constexpr int BH = 128 * HPITCH;           // B stage halves
constexpr int STAGE_H = AH + BH;           // 9216 halves = 18KB
constexpr int GEMM_SMEM = 2 * STAGE_H * 2; // 36864 bytes

template<bool RELU, bool ADDRES>
__global__ void __launch_bounds__(256, 1) gemm_h16(
    const float* __restrict__ A, const float* __restrict__ B,
    const float* __restrict__ bias, const float* __restrict__ Res,
    float* __restrict__ C, float* __restrict__ part,
    int N, int Kd, int KC)
{
    extern __shared__ __half sm[];
    const int tid = threadIdx.x;
    const int wid = tid >> 5, lane = tid & 31;
    const int lr = lane >> 2, lc = lane & 3;
    const int wm = wid & 3, wn = wid >> 2;      // 4 m-warps x 2 n-warps
    const int m0 = blockIdx.x * 256, n0 = blockIdx.y * 128;
    const int Z = gridDim.z, KCz = KC / Z, kc0 = blockIdx.z * KCz;
    const int M = gridDim.x * 256;

    const int ldr = tid >> 2, ldq = tid & 3;    // loader row (0..63), float4 col

    float4 ra[4], rb[2];
    auto ldg = [&](int c) {
        const int ko = (kc0 + c) * 16 + ldq * 4;
        #pragma unroll
        for (int i = 0; i < 4; i++)
            ra[i] = *(const float4*)(A + (size_t)(m0 + ldr + i * 64) * Kd + ko);
        #pragma unroll
        for (int i = 0; i < 2; i++)
            rb[i] = *(const float4*)(B + (size_t)(n0 + ldr + i * 64) * Kd + ko);
    };
    auto sts = [&](int s) {
        __half* d = sm + s * STAGE_H;
        #pragma unroll
        for (int i = 0; i < 4; i++)
            *(uint2*)(d + (ldr + i * 64) * HPITCH + ldq * 4) =
                make_uint2(pk(ra[i].x, ra[i].y), pk(ra[i].z, ra[i].w));
        #pragma unroll
        for (int i = 0; i < 2; i++)
            *(uint2*)(d + AH + (ldr + i * 64) * HPITCH + ldq * 4) =
                make_uint2(pk(rb[i].x, rb[i].y), pk(rb[i].z, rb[i].w));
    };

    float acc[4][8][4];
    #pragma unroll
    for (int mt = 0; mt < 4; mt++)
        #pragma unroll
        for (int nt = 0; nt < 8; nt++)
            #pragma unroll
            for (int q = 0; q < 4; q++) acc[mt][nt][q] = 0.f;

    ldg(0);
    sts(0);
    if (KCz > 1) ldg(1);
    __syncthreads();

    for (int kt = 0; kt < KCz; kt++) {
        const __half* As = sm + (kt & 1) * STAGE_H;
        const __half* Bs = As + AH;
        uint32_t a[4][4], b[8][2];
        #pragma unroll
        for (int mt = 0; mt < 4; mt++) {
            const __half* p = As + (wm * 64 + mt * 16 + lr) * HPITCH + lc * 2;
            a[mt][0] = *(const uint32_t*)(p);
            a[mt][1] = *(const uint32_t*)(p + 8 * HPITCH);
            a[mt][2] = *(const uint32_t*)(p + 8);
            a[mt][3] = *(const uint32_t*)(p + 8 * HPITCH + 8);
        }
        #pragma unroll
        for (int nt = 0; nt < 8; nt++) {
            const __half* q = Bs + (wn * 64 + nt * 8 + lr) * HPITCH + lc * 2;
            b[nt][0] = *(const uint32_t*)(q);
            b[nt][1] = *(const uint32_t*)(q + 8);
        }
        #pragma unroll
        for (int mt = 0; mt < 4; mt++)
            #pragma unroll
            for (int nt = 0; nt < 8; nt++)
                mma_h(acc[mt][nt], a[mt], b[nt]);

        __syncthreads();
        if (kt + 1 < KCz) sts((kt + 1) & 1);
        if (kt + 2 < KCz) ldg(kt + 2);
        __syncthreads();
    }

    if (Z == 1) {
        #pragma unroll
        for (int mt = 0; mt < 4; mt++) {
            #pragma unroll
            for (int nt = 0; nt < 8; nt++) {
                const int row0 = m0 + wm * 64 + mt * 16 + lr;
                const int col  = n0 + wn * 64 + nt * 8 + 2 * lc;
                const float b0 = bias[col], b1 = bias[col + 1];
                float v0 = acc[mt][nt][0] + b0, v1 = acc[mt][nt][1] + b1;
                float v2 = acc[mt][nt][2] + b0, v3 = acc[mt][nt][3] + b1;
                if (ADDRES) {
                    float2 r0 = *(const float2*)(Res + (size_t)row0 * N + col);
                    float2 r1 = *(const float2*)(Res + (size_t)(row0 + 8) * N + col);
                    v0 += r0.x; v1 += r0.y; v2 += r1.x; v3 += r1.y;
                }
                if (RELU) {
                    v0 = fmaxf(v0, 0.f); v1 = fmaxf(v1, 0.f);
                    v2 = fmaxf(v2, 0.f); v3 = fmaxf(v3, 0.f);
                }
                *(float2*)(C + (size_t)row0 * N + col)       = make_float2(v0, v1);
                *(float2*)(C + (size_t)(row0 + 8) * N + col) = make_float2(v2, v3);
            }
        }
    } else {
        float* P = part + (size_t)blockIdx.z * M * N;
        #pragma unroll
        for (int mt = 0; mt < 4; mt++) {
            #pragma unroll
            for (int nt = 0; nt < 8; nt++) {
                const int row0 = m0 + wm * 64 + mt * 16 + lr;
                const int col  = n0 + wn * 64 + nt * 8 + 2 * lc;
                *(float2*)(P + (size_t)row0 * N + col)       = make_float2(acc[mt][nt][0], acc[mt][nt][1]);
                *(float2*)(P + (size_t)(row0 + 8) * N + col) = make_float2(acc[mt][nt][2], acc[mt][nt][3]);
            }
        }
    }
}

// ============================================================
// split-K merge: out = f( sum_z part[z] + bias (+res) ), optional relu
// ============================================================
template<bool RELU, bool ADDRES>
__global__ void __launch_bounds__(256) merge_k(
    const float* __restrict__ part, const float* __restrict__ bias,
    const float* __restrict__ Res, float* __restrict__ out,
    size_t MN, int N, int Z)
{
    const size_t i = ((size_t)blockIdx.x * 256 + threadIdx.x) * 4;
    float4 s = *(const float4*)(part + i);
    for (int z = 1; z < Z; z++) {
        float4 p = *(const float4*)(part + (size_t)z * MN + i);
        s.x += p.x; s.y += p.y; s.z += p.z; s.w += p.w;
    }
    const int col = (int)(i % (size_t)N);
    float4 bb = *(const float4*)(bias + col);
    s.x += bb.x; s.y += bb.y; s.z += bb.z; s.w += bb.w;
    if (ADDRES) {
        float4 rr = *(const float4*)(Res + i);
        s.x += rr.x; s.y += rr.y; s.z += rr.z; s.w += rr.w;
    }
    if (RELU) {
        s.x = fmaxf(s.x, 0.f); s.y = fmaxf(s.y, 0.f);
        s.z = fmaxf(s.z, 0.f); s.w = fmaxf(s.w, 0.f);
    }
    *(float4*)(out + i) = s;
}

// ============================================================
// LayerNorm over Dd per row
// ============================================================
__global__ void __launch_bounds__(256) ln_kernel(
    const float* __restrict__ in, const float* __restrict__ g,
    const float* __restrict__ b, float* __restrict__ out)
{
    const int row = blockIdx.x, t = threadIdx.x;
    const float4* p = (const float4*)(in + (size_t)row * Dd);
    float s = 0.f, s2 = 0.f;
    for (int i = t; i < Dd / 4; i += 256) {
        float4 v = p[i];
        s += v.x + v.y + v.z + v.w;
        s2 += v.x * v.x + v.y * v.y + v.z * v.z + v.w * v.w;
    }
    #pragma unroll
    for (int o = 16; o > 0; o >>= 1) {
        s  += __shfl_xor_sync(~0u, s, o);
        s2 += __shfl_xor_sync(~0u, s2, o);
    }
    __shared__ float rs[8], rs2[8], smean, sinv;
    if ((t & 31) == 0) { rs[t >> 5] = s; rs2[t >> 5] = s2; }
    __syncthreads();
    if (t == 0) {
        float ts = 0.f, ts2 = 0.f;
        #pragma unroll
        for (int i = 0; i < 8; i++) { ts += rs[i]; ts2 += rs2[i]; }
        float mean = ts * (1.f / Dd);
        smean = mean;
        sinv = rsqrtf(ts2 * (1.f / Dd) - mean * mean + 1e-5f);
    }
    __syncthreads();
    const float mean = smean, inv = sinv;
    const float4 *g4 = (const float4*)g, *b4 = (const float4*)b;
    float4* o4 = (float4*)(out + (size_t)row * Dd);
    for (int i = t; i < Dd / 4; i += 256) {
        float4 v = p[i], gg = g4[i], bb = b4[i], r;
        r.x = (v.x - mean) * inv * gg.x + bb.x;
        r.y = (v.y - mean) * inv * gg.y + bb.y;
        r.z = (v.z - mean) * inv * gg.z + bb.z;
        r.w = (v.w - mean) * inv * gg.w + bb.w;
        o4[i] = r;
    }
}

__global__ void __launch_bounds__(128) gap_kernel(
    const float* __restrict__ x, float* __restrict__ gap)
{
    const float* p = x + ((size_t)blockIdx.x * Cc + threadIdx.x) * 49;
    float a = 0.f;
    #pragma unroll
    for (int i = 0; i < 49; i++) a += p[i];
    gap[(size_t)blockIdx.x * Cc + threadIdx.x] = a * (1.f / 49.f);
}

// ============================================================
// Per-sample grouped dynamic 3x3 conv + residual
// ============================================================
__global__ void __launch_bounds__(128) dynconv_kernel(
    const float* __restrict__ x, const float* __restrict__ dyn,
    float* __restrict__ out)
{
    const int s = blockIdx.x, t = threadIdx.x;
    __shared__ float sIn[Cc][81];
    float* sc = sIn[t];
    #pragma unroll
    for (int i = 0; i < 81; i++) sc[i] = 0.f;
    const float* xp = x + ((size_t)s * Cc + t) * 49;
    #pragma unroll
    for (int y = 0; y < 7; y++)
        #pragma unroll
        for (int xx = 0; xx < 7; xx++)
            sc[(y + 1) * 9 + xx + 1] = xp[y * 7 + xx];
    __syncthreads();

    const int grp = t >> 5;
    const float* wb = dyn + (size_t)s * DYN + (size_t)t * (CPG * 9);
    const float* ib = &sIn[grp * CPG][0];
    float acc[49];
    #pragma unroll
    for (int i = 0; i < 49; i++) acc[i] = 0.f;
    for (int ic = 0; ic < CPG; ic++) {
        const float* w = wb + ic * 9;
        const float* in = ib + ic * 81;
        float w0 = w[0], w1 = w[1], w2 = w[2], w3 = w[3], w4 = w[4];
        float w5 = w[5], w6 = w[6], w7 = w[7], w8 = w[8];
        #pragma unroll
        for (int y = 0; y < 7; y++) {
            #pragma unroll
            for (int xx = 0; xx < 7; xx++) {
                float a = acc[y * 7 + xx];
                a += w0 * in[y * 9 + xx]       + w1 * in[y * 9 + xx + 1]       + w2 * in[y * 9 + xx + 2];
                a += w3 * in[(y + 1) * 9 + xx] + w4 * in[(y + 1) * 9 + xx + 1] + w5 * in[(y + 1) * 9 + xx + 2];
                a += w6 * in[(y + 2) * 9 + xx] + w7 * in[(y + 2) * 9 + xx + 1] + w8 * in[(y + 2) * 9 + xx + 2];
                acc[y * 7 + xx] = a;
            }
        }
    }
    float* op = out + ((size_t)s * Cc + t) * 49;
    const float* ms = sIn[t];
    #pragma unroll
    for (int y = 0; y < 7; y++)
        #pragma unroll
        for (int xx = 0; xx < 7; xx++)
            op[y * 7 + xx] = acc[y * 7 + xx] + ms[(y + 1) * 9 + xx + 1];
}

// ============================================================
// cost matrix
// ============================================================
__global__ void __launch_bounds__(256) cost_kernel(
    const float* __restrict__ rb, const float* __restrict__ cb, float* __restrict__ out)
{
    __shared__ float sR[Mb * 4], sC[Mb * 4], sdist[Mb * Mb], rm[8], sMax;
    const int t = threadIdx.x;
    sR[t] = rb[t]; sC[t] = cb[t];
    __syncthreads();
    float lm = 0.f;
    for (int idx = t; idx < Mb * Mb; idx += 256) {
        int i = idx >> 6, j = idx & 63;
        float d = fabsf((sR[i * 4] + sR[i * 4 + 2]) * 0.5f - (sC[j * 4] + sC[j * 4 + 2]) * 0.5f)
                + fabsf((sR[i * 4 + 1] + sR[i * 4 + 3]) * 0.5f - (sC[j * 4 + 1] + sC[j * 4 + 3]) * 0.5f);
        sdist[idx] = d;
        lm = fmaxf(lm, d);
    }
    #pragma unroll
    for (int o = 16; o > 0; o >>= 1) lm = fmaxf(lm, __shfl_xor_sync(~0u, lm, o));
    if ((t & 31) == 0) rm[t >> 5] = lm;
    __syncthreads();
    if (t == 0) {
        float m = 0.f;
        #pragma unroll
        for (int i = 0; i < 8; i++) m = fmaxf(m, rm[i]);
        sMax = fmaxf(m, 1.f);
    }
    __syncthreads();
    const float dmax = sMax;
    for (int idx = t; idx < Mb * Mb; idx += 256) {
        int i = idx >> 6, j = idx & 63;
        float ax0 = sR[i*4], ay0 = sR[i*4+1], ax1 = sR[i*4+2], ay1 = sR[i*4+3];
        float bx0 = sC[j*4], by0 = sC[j*4+1], bx1 = sC[j*4+2], by1 = sC[j*4+3];
        float areaA = (ax1 - ax0) * (ay1 - ay0), areaB = (bx1 - bx0) * (by1 - by0);
        float w = fmaxf(fminf(ax1, bx1) - fmaxf(ax0, bx0), 0.f);
        float h = fmaxf(fminf(ay1, by1) - fmaxf(ay0, by0), 0.f);
        float inter = w * h;
        out[idx] = -inter / (areaA + areaB - inter) + 0.5f * sdist[idx] / dmax;
    }
}

// ============================================================
// host launcher
// ============================================================
extern "C" void kernel_launch(void* const* d_in, const int* in_sizes, int n_in,
                              void* d_out, int out_size)
{
    const float* wf     = (const float*)d_in[0];
    const float* rf     = (const float*)d_in[1];
    const float* refb   = (const float*)d_in[2];
    const float* curb   = (const float*)d_in[3];
    // d_in[4..7] = wq,bq,wk,bk: dead (softmax over one key == 1 -> attn == v)
    const float* wv     = (const float*)d_in[8];
    const float* bv     = (const float*)d_in[9];
    const float* wo     = (const float*)d_in[10];
    const float* bo     = (const float*)d_in[11];
    const float* g1     = (const float*)d_in[12];
    const float* b1     = (const float*)d_in[13];
    const float* wgen_w = (const float*)d_in[14];
    const float* wgen_b = (const float*)d_in[15];
    const float* g2     = (const float*)d_in[16];
    const float* b2     = (const float*)d_in[17];
    const float* wf1    = (const float*)d_in[18];
    const float* bf1    = (const float*)d_in[19];
    const float* wf2    = (const float*)d_in[20];
    const float* bf2    = (const float*)d_in[21];
    const float* g3     = (const float*)d_in[22];
    const float* b3     = (const float*)d_in[23];
    float* out = (float*)d_out;

    float *v, *bufA, *x, *flat, *gap, *dyn, *h, *part;
    cudaGetSymbolAddress((void**)&v, g_v);       cudaGetSymbolAddress((void**)&bufA, g_bufA);
    cudaGetSymbolAddress((void**)&x, g_x);       cudaGetSymbolAddress((void**)&flat, g_flat);
    cudaGetSymbolAddress((void**)&gap, g_gap);   cudaGetSymbolAddress((void**)&dyn, g_dyn);
    cudaGetSymbolAddress((void**)&h, g_h);       cudaGetSymbolAddress((void**)&part, g_part);

    cudaFuncSetAttribute(gemm_h16<false, false>, cudaFuncAttributeMaxDynamicSharedMemorySize, GEMM_SMEM);
    cudaFuncSetAttribute(gemm_h16<false, true>,  cudaFuncAttributeMaxDynamicSharedMemorySize, GEMM_SMEM);

    const size_t MN1 = (size_t)Kn * Dd;     // 6.42M
    const size_t MNF = (size_t)Kn * FFNn;   // 1.05M

    // 1. v = rf @ wv^T + bv              (split-K2)
    gemm_h16<false, false><<<dim3(4, 49, 2), 256, GEMM_SMEM>>>(rf, wv, bv, nullptr, v, part, Dd, Dd, 392);
    merge_k<false, false><<<(int)(MN1 / 1024), 256>>>(part, bv, nullptr, v, MN1, Dd, 2);
    // 2. bufA = v @ wo^T + bo + wf       (split-K2)
    gemm_h16<false, false><<<dim3(4, 49, 2), 256, GEMM_SMEM>>>(v, wo, bo, nullptr, bufA, part, Dd, Dd, 392);
    merge_k<false, true><<<(int)(MN1 / 1024), 256>>>(part, bo, wf, bufA, MN1, Dd, 2);
    // 3. x = LN(bufA)
    ln_kernel<<<Kn, 256>>>(bufA, g1, b1, x);
    // 4. gap
    gap_kernel<<<Kn, 128>>>(x, gap);
    // 5. dyn = gap @ wgen^T + wgen_b     (Z=1, 1152 CTAs)
    gemm_h16<false, false><<<dim3(4, 288, 1), 256, GEMM_SMEM>>>(gap, wgen_w, wgen_b, nullptr, dyn, part, DYN, Cc, 8);
    // 6. bufA = dynconv(x) + x
    dynconv_kernel<<<Kn, 128>>>(x, dyn, bufA);
    // 7. flat = LN(bufA)
    ln_kernel<<<Kn, 256>>>(bufA, g2, b2, flat);
    // 8. h = relu(flat @ wf1^T + bf1)    (split-K4)
    gemm_h16<false, false><<<dim3(4, 8, 4), 256, GEMM_SMEM>>>(flat, wf1, bf1, nullptr, h, part, FFNn, Dd, 392);
    merge_k<true, false><<<(int)(MNF / 1024), 256>>>(part, bf1, nullptr, h, MNF, FFNn, 4);
    // 9. bufA = h @ wf2^T + bf2 + flat   (Z=1 direct)
    gemm_h16<false, true><<<dim3(4, 49, 1), 256, GEMM_SMEM>>>(h, wf2, bf2, flat, bufA, part, Dd, FFNn, 64);
    // 10. out = LN(bufA)
    ln_kernel<<<Kn, 256>>>(bufA, g3, b3, out);
    // 11. cost matrix
    cost_kernel<<<1, 256>>>(refb, curb, out + (size_t)Kn * Dd);
}

// round 11
// speedup vs baseline: 1.1322x; 1.1322x over previous
#include <cuda_runtime.h>
#include <cuda_fp16.h>
#include <cstdint>
#include <cstddef>

constexpr int Kn = 1024, Cc = 128, Dd = 6272, FFNn = 1024, CPG = 32, DYN = 36864, Mb = 64;

// ---------------- scratch ----------------
__device__ __align__(128) float  g_v   [(size_t)Kn * Dd];
__device__ __align__(128) float  g_x   [(size_t)Kn * Dd];
__device__ __align__(128) float  g_flat[(size_t)Kn * Dd];
__device__ __align__(128) float  g_gap [(size_t)Kn * Cc];
__device__ __align__(128) __half g_dynh[(size_t)Kn * DYN];
__device__ __align__(128) float  g_h   [(size_t)Kn * FFNn];
__device__ __align__(128) float  g_part[(size_t)2 * Kn * Dd];   // up to Z*M*N partials

// ---------------- PTX helpers ----------------
__device__ __forceinline__ float f2tf(float x) {
    uint32_t r;
    asm("cvt.rna.tf32.f32 %0, %1;" : "=r"(r) : "f"(x));
    return __uint_as_float(r);
}
__device__ __forceinline__ void mma_tf32(float* c, const uint32_t* a, const uint32_t* b) {
    asm volatile(
        "mma.sync.aligned.m16n8k8.row.col.f32.tf32.tf32.f32 "
        "{%0,%1,%2,%3}, {%4,%5,%6,%7}, {%8,%9}, {%0,%1,%2,%3};"
        : "+f"(c[0]), "+f"(c[1]), "+f"(c[2]), "+f"(c[3])
        : "r"(a[0]), "r"(a[1]), "r"(a[2]), "r"(a[3]), "r"(b[0]), "r"(b[1]));
}
#define CP_A16(dst, src) \
    asm volatile("cp.async.ca.shared.global [%0], [%1], 16;" :: "r"(dst), "l"(src) : "memory")
#define CP_COMMIT() asm volatile("cp.async.commit_group;" ::: "memory")
#define CP_WAIT1()  asm volatile("cp.async.wait_group 1;" ::: "memory")

// ============================================================
// tf32 GEMM (R5 mainloop): 128x128 block, 8 warps (32x64), occ 2,
// 3-stage cp.async, in-loop cvt. Z-way split-K via gridDim.z:
// Z==1 -> C (+bias, optionally fp16 out), Z>1 -> raw partials.
// ============================================================
constexpr int SROW = 20;
constexpr int STAGE_F = 2 * 128 * SROW;     // 5120 floats
constexpr int GEMM_SMEM = 3 * STAGE_F * 4;  // 61440 B

template<bool OUTHALF>
__global__ void __launch_bounds__(256, 2) gemm_t(
    const float* __restrict__ A, const float* __restrict__ B,
    const float* __restrict__ bias, float* __restrict__ Cf,
    __half* __restrict__ Ch, float* __restrict__ part,
    int N, int Kd, int KC)
{
    extern __shared__ float sm[];
    const int tid = threadIdx.x;
    const int wid = tid >> 5, lane = tid & 31;
    const int lr = lane >> 2, lc = lane & 3;
    const int m0 = blockIdx.x * 128, n0 = blockIdx.y * 128;
    const int wrow = (wid >> 1) * 32, wcol = (wid & 1) * 64;
    const int Z = gridDim.z, KCz = KC / Z, kc0 = blockIdx.z * KCz;
    const int M = gridDim.x * 128;

    const uint32_t smem_base = (uint32_t)__cvta_generic_to_shared(sm);
    const int c0r = tid >> 2, c0q = tid & 3;
    const int c1r = (tid + 256) >> 2;

    const float* Abase = A + (size_t)m0 * Kd;
    const float* Bbase = B + (size_t)n0 * Kd;

    auto load_stage = [&](int s, int kt) {
        const uint32_t base = smem_base + (uint32_t)s * (STAGE_F * 4);
        const int ko = (kc0 + kt) * 16;
        CP_A16(base + (uint32_t)(c0r * SROW + c0q * 4) * 4,              Abase + (size_t)c0r * Kd + ko + c0q * 4);
        CP_A16(base + (uint32_t)(c1r * SROW + c0q * 4) * 4,              Abase + (size_t)c1r * Kd + ko + c0q * 4);
        CP_A16(base + (uint32_t)(128 * SROW + c0r * SROW + c0q * 4) * 4, Bbase + (size_t)c0r * Kd + ko + c0q * 4);
        CP_A16(base + (uint32_t)(128 * SROW + c1r * SROW + c0q * 4) * 4, Bbase + (size_t)c1r * Kd + ko + c0q * 4);
    };

    float acc[2][8][4];
    #pragma unroll
    for (int mt = 0; mt < 2; mt++)
        #pragma unroll
        for (int nt = 0; nt < 8; nt++)
            #pragma unroll
            for (int q = 0; q < 4; q++) acc[mt][nt][q] = 0.f;

    load_stage(0, 0); CP_COMMIT();
    if (KCz > 1) load_stage(1, 1);
    CP_COMMIT();

    for (int kt = 0; kt < KCz; ++kt) {
        CP_WAIT1();
        __syncthreads();
        const int nx = kt + 2;
        if (nx < KCz) load_stage(nx % 3, nx);
        CP_COMMIT();

        const float* As = sm + (kt % 3) * STAGE_F;
        const float* Bs = As + 128 * SROW;
        #pragma unroll
        for (int kk = 0; kk < 2; kk++) {
            const int kb = kk * 8;
            uint32_t a[2][4], b[8][2];
            #pragma unroll
            for (int mt = 0; mt < 2; mt++) {
                const int r = wrow + mt * 16 + lr;
                a[mt][0] = __float_as_uint(f2tf(As[r * SROW + kb + lc]));
                a[mt][1] = __float_as_uint(f2tf(As[(r + 8) * SROW + kb + lc]));
                a[mt][2] = __float_as_uint(f2tf(As[r * SROW + kb + lc + 4]));
                a[mt][3] = __float_as_uint(f2tf(As[(r + 8) * SROW + kb + lc + 4]));
            }
            #pragma unroll
            for (int nt = 0; nt < 8; nt++) {
                const int n = wcol + nt * 8 + lr;
                b[nt][0] = __float_as_uint(f2tf(Bs[n * SROW + kb + lc]));
                b[nt][1] = __float_as_uint(f2tf(Bs[n * SROW + kb + lc + 4]));
            }
            #pragma unroll
            for (int mt = 0; mt < 2; mt++)
                #pragma unroll
                for (int nt = 0; nt < 8; nt++)
                    mma_tf32(acc[mt][nt], a[mt], b[nt]);
        }
    }

    if (Z == 1) {
        #pragma unroll
        for (int mt = 0; mt < 2; mt++) {
            #pragma unroll
            for (int nt = 0; nt < 8; nt++) {
                const int row0 = m0 + wrow + mt * 16 + lr;
                const int col  = n0 + wcol + nt * 8 + 2 * lc;
                const float b0 = bias[col], b1 = bias[col + 1];
                float v0 = acc[mt][nt][0] + b0, v1 = acc[mt][nt][1] + b1;
                float v2 = acc[mt][nt][2] + b0, v3 = acc[mt][nt][3] + b1;
                if (OUTHALF) {
                    *(__half2*)(Ch + (size_t)row0 * N + col)       = __floats2half2_rn(v0, v1);
                    *(__half2*)(Ch + (size_t)(row0 + 8) * N + col) = __floats2half2_rn(v2, v3);
                } else {
                    *(float2*)(Cf + (size_t)row0 * N + col)       = make_float2(v0, v1);
                    *(float2*)(Cf + (size_t)(row0 + 8) * N + col) = make_float2(v2, v3);
                }
            }
        }
    } else {
        float* P = part + (size_t)blockIdx.z * M * N;
        #pragma unroll
        for (int mt = 0; mt < 2; mt++) {
            #pragma unroll
            for (int nt = 0; nt < 8; nt++) {
                const int row0 = m0 + wrow + mt * 16 + lr;
                const int col  = n0 + wcol + nt * 8 + 2 * lc;
                *(float2*)(P + (size_t)row0 * N + col)       = make_float2(acc[mt][nt][0], acc[mt][nt][1]);
                *(float2*)(P + (size_t)(row0 + 8) * N + col) = make_float2(acc[mt][nt][2], acc[mt][nt][3]);
            }
        }
    }
}

// ============================================================
// split-K merge (elementwise): out = f(sum_z part + bias), opt relu
// ============================================================
template<bool RELU>
__global__ void __launch_bounds__(256) merge_plain(
    const float* __restrict__ part, const float* __restrict__ bias,
    float* __restrict__ out, size_t MN, int N, int Z)
{
    const size_t i = ((size_t)blockIdx.x * 256 + threadIdx.x) * 4;
    float4 s = *(const float4*)(part + i);
    for (int z = 1; z < Z; z++) {
        float4 p = *(const float4*)(part + (size_t)z * MN + i);
        s.x += p.x; s.y += p.y; s.z += p.z; s.w += p.w;
    }
    float4 bb = *(const float4*)(bias + (i % (size_t)N));
    s.x += bb.x; s.y += bb.y; s.z += bb.z; s.w += bb.w;
    if (RELU) {
        s.x = fmaxf(s.x, 0.f); s.y = fmaxf(s.y, 0.f);
        s.z = fmaxf(s.z, 0.f); s.w = fmaxf(s.w, 0.f);
    }
    *(float4*)(out + i) = s;
}

// ============================================================
// merge + residual + LayerNorm (+ optional GAP of normalized x)
// one block per row; val = sum_z part + bias + res; out = LN(val)*g+b
// ============================================================
__global__ void __launch_bounds__(256) merge_ln(
    const float* __restrict__ part, const float* __restrict__ bias,
    const float* __restrict__ res, const float* __restrict__ gamma,
    const float* __restrict__ beta, float* __restrict__ out,
    float* __restrict__ gapOut, int N, int Z, size_t MN)
{
    const int row = blockIdx.x, t = threadIdx.x;
    const size_t base = (size_t)row * N;
    __shared__ float rs[8], rs2[8], smean, sinv, chs[Cc];

    float s = 0.f, s2 = 0.f;
    for (int i = t * 4; i < N; i += 1024) {
        float4 v = *(const float4*)(part + base + i);
        for (int z = 1; z < Z; z++) {
            float4 p = *(const float4*)(part + (size_t)z * MN + base + i);
            v.x += p.x; v.y += p.y; v.z += p.z; v.w += p.w;
        }
        float4 bb = *(const float4*)(bias + i);
        float4 rr = *(const float4*)(res + base + i);
        v.x += bb.x + rr.x; v.y += bb.y + rr.y;
        v.z += bb.z + rr.z; v.w += bb.w + rr.w;
        s  += v.x + v.y + v.z + v.w;
        s2 += v.x * v.x + v.y * v.y + v.z * v.z + v.w * v.w;
    }
    #pragma unroll
    for (int o = 16; o > 0; o >>= 1) {
        s  += __shfl_xor_sync(~0u, s, o);
        s2 += __shfl_xor_sync(~0u, s2, o);
    }
    if ((t & 31) == 0) { rs[t >> 5] = s; rs2[t >> 5] = s2; }
    if (gapOut && t < Cc) chs[t] = 0.f;
    __syncthreads();
    if (t == 0) {
        float ts = 0.f, ts2 = 0.f;
        #pragma unroll
        for (int i = 0; i < 8; i++) { ts += rs[i]; ts2 += rs2[i]; }
        float mean = ts / N;
        smean = mean;
        sinv = rsqrtf(ts2 / N - mean * mean + 1e-5f);
    }
    __syncthreads();
    const float mean = smean, inv = sinv;

    for (int i = t * 4; i < N; i += 1024) {
        float4 v = *(const float4*)(part + base + i);
        for (int z = 1; z < Z; z++) {
            float4 p = *(const float4*)(part + (size_t)z * MN + base + i);
            v.x += p.x; v.y += p.y; v.z += p.z; v.w += p.w;
        }
        float4 bb = *(const float4*)(bias + i);
        float4 rr = *(const float4*)(res + base + i);
        float4 gg = *(const float4*)(gamma + i);
        float4 be = *(const float4*)(beta + i);
        float x0 = (v.x + bb.x + rr.x - mean) * inv * gg.x + be.x;
        float x1 = (v.y + bb.y + rr.y - mean) * inv * gg.y + be.y;
        float x2 = (v.z + bb.z + rr.z - mean) * inv * gg.z + be.z;
        float x3 = (v.w + bb.w + rr.w - mean) * inv * gg.w + be.w;
        *(float4*)(out + base + i) = make_float4(x0, x1, x2, x3);
        if (gapOut) {
            atomicAdd(&chs[i / 49], x0);
            atomicAdd(&chs[(i + 1) / 49], x1);
            atomicAdd(&chs[(i + 2) / 49], x2);
            atomicAdd(&chs[(i + 3) / 49], x3);
        }
    }
    if (gapOut) {
        __syncthreads();
        if (t < Cc) gapOut[(size_t)row * Cc + t] = chs[t] * (1.f / 49.f);
    }
}

// ============================================================
// dynconv (fp16 dyn weights) + residual + fused LN2 (per-element g2,b2)
// one block per sample, one thread per output channel
// ============================================================
__global__ void __launch_bounds__(128) dynconv_ln(
    const float* __restrict__ x, const __half* __restrict__ dyn,
    const float* __restrict__ g2, const float* __restrict__ b2,
    float* __restrict__ out)
{
    const int s = blockIdx.x, t = threadIdx.x;
    __shared__ float sIn[Cc][81];
    __shared__ float rs[4], rs2[4], smean, sinv;
    float* sc = sIn[t];
    #pragma unroll
    for (int i = 0; i < 81; i++) sc[i] = 0.f;
    const float* xp = x + ((size_t)s * Cc + t) * 49;
    #pragma unroll
    for (int y = 0; y < 7; y++)
        #pragma unroll
        for (int xx = 0; xx < 7; xx++)
            sc[(y + 1) * 9 + xx + 1] = xp[y * 7 + xx];
    __syncthreads();

    const int grp = t >> 5;
    const __half* wb = dyn + (size_t)s * DYN + (size_t)t * (CPG * 9);
    const float* ib = &sIn[grp * CPG][0];
    float acc[49];
    #pragma unroll
    for (int i = 0; i < 49; i++) acc[i] = 0.f;
    for (int ic = 0; ic < CPG; ic++) {
        const __half* w = wb + ic * 9;
        const float* in = ib + ic * 81;
        float w0 = __half2float(w[0]), w1 = __half2float(w[1]), w2 = __half2float(w[2]);
        float w3 = __half2float(w[3]), w4 = __half2float(w[4]), w5 = __half2float(w[5]);
        float w6 = __half2float(w[6]), w7 = __half2float(w[7]), w8 = __half2float(w[8]);
        #pragma unroll
        for (int y = 0; y < 7; y++) {
            #pragma unroll
            for (int xx = 0; xx < 7; xx++) {
                float a = acc[y * 7 + xx];
                a += w0 * in[y * 9 + xx]       + w1 * in[y * 9 + xx + 1]       + w2 * in[y * 9 + xx + 2];
                a += w3 * in[(y + 1) * 9 + xx] + w4 * in[(y + 1) * 9 + xx + 1] + w5 * in[(y + 1) * 9 + xx + 2];
                a += w6 * in[(y + 2) * 9 + xx] + w7 * in[(y + 2) * 9 + xx + 1] + w8 * in[(y + 2) * 9 + xx + 2];
                acc[y * 7 + xx] = a;
            }
        }
    }
    // y = conv + residual
    const float* ms = sIn[t];
    float ss = 0.f, ss2 = 0.f;
    #pragma unroll
    for (int j = 0; j < 49; j++) {
        float yv = acc[j] + ms[(j / 7 + 1) * 9 + (j % 7) + 1];
        acc[j] = yv;
        ss += yv; ss2 += yv * yv;
    }
    #pragma unroll
    for (int o = 16; o > 0; o >>= 1) {
        ss  += __shfl_xor_sync(~0u, ss, o);
        ss2 += __shfl_xor_sync(~0u, ss2, o);
    }
    if ((t & 31) == 0) { rs[t >> 5] = ss; rs2[t >> 5] = ss2; }
    __syncthreads();
    if (t == 0) {
        float ts = rs[0] + rs[1] + rs[2] + rs[3];
        float ts2 = rs2[0] + rs2[1] + rs2[2] + rs2[3];
        float mean = ts / Dd;
        smean = mean;
        sinv = rsqrtf(ts2 / Dd - mean * mean + 1e-5f);
    }
    __syncthreads();
    const float mean = smean, inv = sinv;
    float* op = out + ((size_t)s * Cc + t) * 49;
    const float* gp = g2 + t * 49;
    const float* bp = b2 + t * 49;
    #pragma unroll
    for (int j = 0; j < 49; j++)
        op[j] = (acc[j] - mean) * inv * gp[j] + bp[j];
}

// ============================================================
// cost matrix
// ============================================================
__global__ void __launch_bounds__(256) cost_kernel(
    const float* __restrict__ rb, const float* __restrict__ cb, float* __restrict__ out)
{
    __shared__ float sR[Mb * 4], sC[Mb * 4], sdist[Mb * Mb], rm[8], sMax;
    const int t = threadIdx.x;
    sR[t] = rb[t]; sC[t] = cb[t];
    __syncthreads();
    float lm = 0.f;
    for (int idx = t; idx < Mb * Mb; idx += 256) {
        int i = idx >> 6, j = idx & 63;
        float d = fabsf((sR[i * 4] + sR[i * 4 + 2]) * 0.5f - (sC[j * 4] + sC[j * 4 + 2]) * 0.5f)
                + fabsf((sR[i * 4 + 1] + sR[i * 4 + 3]) * 0.5f - (sC[j * 4 + 1] + sC[j * 4 + 3]) * 0.5f);
        sdist[idx] = d;
        lm = fmaxf(lm, d);
    }
    #pragma unroll
    for (int o = 16; o > 0; o >>= 1) lm = fmaxf(lm, __shfl_xor_sync(~0u, lm, o));
    if ((t & 31) == 0) rm[t >> 5] = lm;
    __syncthreads();
    if (t == 0) {
        float m = 0.f;
        #pragma unroll
        for (int i = 0; i < 8; i++) m = fmaxf(m, rm[i]);
        sMax = fmaxf(m, 1.f);
    }
    __syncthreads();
    const float dmax = sMax;
    for (int idx = t; idx < Mb * Mb; idx += 256) {
        int i = idx >> 6, j = idx & 63;
        float ax0 = sR[i*4], ay0 = sR[i*4+1], ax1 = sR[i*4+2], ay1 = sR[i*4+3];
        float bx0 = sC[j*4], by0 = sC[j*4+1], bx1 = sC[j*4+2], by1 = sC[j*4+3];
        float areaA = (ax1 - ax0) * (ay1 - ay0), areaB = (bx1 - bx0) * (by1 - by0);
        float w = fmaxf(fminf(ax1, bx1) - fmaxf(ax0, bx0), 0.f);
        float h = fmaxf(fminf(ay1, by1) - fmaxf(ay0, by0), 0.f);
        float inter = w * h;
        out[idx] = -inter / (areaA + areaB - inter) + 0.5f * sdist[idx] / dmax;
    }
}

// ============================================================
// host launcher
// ============================================================
extern "C" void kernel_launch(void* const* d_in, const int* in_sizes, int n_in,
                              void* d_out, int out_size)
{
    const float* wf     = (const float*)d_in[0];
    const float* rf     = (const float*)d_in[1];
    const float* refb   = (const float*)d_in[2];
    const float* curb   = (const float*)d_in[3];
    // d_in[4..7] dead (softmax over one key == 1 -> attn == v)
    const float* wv     = (const float*)d_in[8];
    const float* bv     = (const float*)d_in[9];
    const float* wo     = (const float*)d_in[10];
    const float* bo     = (const float*)d_in[11];
    const float* g1     = (const float*)d_in[12];
    const float* b1     = (const float*)d_in[13];
    const float* wgen_w = (const float*)d_in[14];
    const float* wgen_b = (const float*)d_in[15];
    const float* g2     = (const float*)d_in[16];
    const float* b2     = (const float*)d_in[17];
    const float* wf1    = (const float*)d_in[18];
    const float* bf1    = (const float*)d_in[19];
    const float* wf2    = (const float*)d_in[20];
    const float* bf2    = (const float*)d_in[21];
    const float* g3     = (const float*)d_in[22];
    const float* b3     = (const float*)d_in[23];
    float* out = (float*)d_out;

    float *v, *x, *flat, *gap, *h, *part;
    __half* dynh;
    cudaGetSymbolAddress((void**)&v, g_v);       cudaGetSymbolAddress((void**)&x, g_x);
    cudaGetSymbolAddress((void**)&flat, g_flat); cudaGetSymbolAddress((void**)&gap, g_gap);
    cudaGetSymbolAddress((void**)&dynh, g_dynh); cudaGetSymbolAddress((void**)&h, g_h);
    cudaGetSymbolAddress((void**)&part, g_part);

    cudaFuncSetAttribute(gemm_t<false>, cudaFuncAttributeMaxDynamicSharedMemorySize, GEMM_SMEM);
    cudaFuncSetAttribute(gemm_t<true>,  cudaFuncAttributeMaxDynamicSharedMemorySize, GEMM_SMEM);

    const size_t MN1 = (size_t)Kn * Dd;     // 6.42M
    const size_t MNF = (size_t)Kn * FFNn;   // 1.05M

    // 1. v = rf @ wv^T + bv                        (Z=2)
    gemm_t<false><<<dim3(8, 49, 2), 256, GEMM_SMEM>>>(rf, wv, bv, nullptr, nullptr, part, Dd, Dd, 392);
    merge_plain<false><<<(int)(MN1 / 1024), 256>>>(part, bv, v, MN1, Dd, 2);
    // 2. x = LN1(v @ wo^T + bo + wf), gap           (Z=2, fused merge+LN+GAP)
    gemm_t<false><<<dim3(8, 49, 2), 256, GEMM_SMEM>>>(v, wo, bo, nullptr, nullptr, part, Dd, Dd, 392);
    merge_ln<<<Kn, 256>>>(part, bo, wf, g1, b1, x, gap, Dd, 2, MN1);
    // 3. dyn(half) = gap @ wgen^T + wgen_b          (Z=1, fp16 out)
    gemm_t<true><<<dim3(8, 288, 1), 256, GEMM_SMEM>>>(gap, wgen_w, wgen_b, nullptr, dynh, part, DYN, Cc, 8);
    // 4. flat = LN2(dynconv(x) + x)                 (fused conv+res+LN)
    dynconv_ln<<<Kn, 128>>>(x, dynh, g2, b2, flat);
    // 5. h = relu(flat @ wf1^T + bf1)               (Z=4)
    gemm_t<false><<<dim3(8, 8, 4), 256, GEMM_SMEM>>>(flat, wf1, bf1, nullptr, nullptr, part, FFNn, Dd, 392);
    merge_plain<true><<<(int)(MNF / 1024), 256>>>(part, bf1, h, MNF, FFNn, 4);
    // 6. out = LN3(h @ wf2^T + bf2 + flat)          (Z=2, fused merge+LN)
    gemm_t<false><<<dim3(8, 49, 2), 256, GEMM_SMEM>>>(h, wf2, bf2, nullptr, nullptr, part, Dd, FFNn, 64);
    merge_ln<<<Kn, 256>>>(part, bf2, flat, g3, b3, out, nullptr, Dd, 2, MN1);
    // 7. cost matrix
    cost_kernel<<<1, 256>>>(refb, curb, out + (size_t)Kn * Dd);
}

// round 15
// speedup vs baseline: 1.2518x; 1.1056x over previous
#include <cuda_runtime.h>
#include <cuda_fp16.h>
#include <cstdint>
#include <cstddef>

constexpr int Kn = 1024, Cc = 128, Dd = 6272, FFNn = 1024, CPG = 32, DYN = 36864, Mb = 64;

// ---------------- scratch ----------------
__device__ __align__(128) float  g_v   [(size_t)Kn * Dd];
__device__ __align__(128) float  g_x   [(size_t)Kn * Dd];
__device__ __align__(128) float  g_flat[(size_t)Kn * Dd];
__device__ __align__(128) float  g_gap [(size_t)Kn * Cc];
__device__ __align__(128) __half g_dynh[(size_t)Kn * DYN];
__device__ __align__(128) float  g_h   [(size_t)Kn * FFNn];
__device__ __align__(128) float  g_part[(size_t)3 * Kn * Dd];   // Z<=3 partials (Z=4 FFN1 fits: 4*Kn*FFNn < 3*Kn*Dd)

// ---------------- PTX helpers ----------------
__device__ __forceinline__ float f2tf(float x) {
    uint32_t r;
    asm("cvt.rna.tf32.f32 %0, %1;" : "=r"(r) : "f"(x));
    return __uint_as_float(r);
}
__device__ __forceinline__ void mma_tf32(float* c, const uint32_t* a, const uint32_t* b) {
    asm volatile(
        "mma.sync.aligned.m16n8k8.row.col.f32.tf32.tf32.f32 "
        "{%0,%1,%2,%3}, {%4,%5,%6,%7}, {%8,%9}, {%0,%1,%2,%3};"
        : "+f"(c[0]), "+f"(c[1]), "+f"(c[2]), "+f"(c[3])
        : "r"(a[0]), "r"(a[1]), "r"(a[2]), "r"(a[3]), "r"(b[0]), "r"(b[1]));
}
#define CP_A16(dst, src) \
    asm volatile("cp.async.ca.shared.global [%0], [%1], 16;" :: "r"(dst), "l"(src) : "memory")
#define CP_COMMIT() asm volatile("cp.async.commit_group;" ::: "memory")
#define CP_WAIT1()  asm volatile("cp.async.wait_group 1;" ::: "memory")

// ============================================================
// tf32 GEMM: 128x128 block, 8 warps (32x64), occ 2, 3-stage cp.async,
// in-loop cvt. gridDim.z = Z-way split-K (variable per-z KC for Z=3).
// Z==1 -> C (+bias, fp32 or fp16 out), Z>1 -> raw partials.
// ============================================================
constexpr int SROW = 20;
constexpr int STAGE_F = 2 * 128 * SROW;     // 5120 floats
constexpr int GEMM_SMEM = 3 * STAGE_F * 4;  // 61440 B

template<bool OUTHALF>
__global__ void __launch_bounds__(256, 2) gemm_t(
    const float* __restrict__ A, const float* __restrict__ B,
    const float* __restrict__ bias, float* __restrict__ Cf,
    __half* __restrict__ Ch, float* __restrict__ part,
    int N, int Kd, int KC)
{
    extern __shared__ float sm[];
    const int tid = threadIdx.x;
    const int wid = tid >> 5, lane = tid & 31;
    const int lr = lane >> 2, lc = lane & 3;
    const int m0 = blockIdx.x * 128, n0 = blockIdx.y * 128;
    const int wrow = (wid >> 1) * 32, wcol = (wid & 1) * 64;
    const int Z = gridDim.z;
    const int KCn = (KC + Z - 1) / Z;
    const int kc0 = blockIdx.z * KCn;
    const int KCz = min(KCn, KC - kc0);
    const int M = gridDim.x * 128;

    const uint32_t smem_base = (uint32_t)__cvta_generic_to_shared(sm);
    const int c0r = tid >> 2, c0q = tid & 3;
    const int c1r = (tid + 256) >> 2;

    const float* Abase = A + (size_t)m0 * Kd;
    const float* Bbase = B + (size_t)n0 * Kd;

    auto load_stage = [&](int s, int kt) {
        const uint32_t base = smem_base + (uint32_t)s * (STAGE_F * 4);
        const int ko = (kc0 + kt) * 16;
        CP_A16(base + (uint32_t)(c0r * SROW + c0q * 4) * 4,              Abase + (size_t)c0r * Kd + ko + c0q * 4);
        CP_A16(base + (uint32_t)(c1r * SROW + c0q * 4) * 4,              Abase + (size_t)c1r * Kd + ko + c0q * 4);
        CP_A16(base + (uint32_t)(128 * SROW + c0r * SROW + c0q * 4) * 4, Bbase + (size_t)c0r * Kd + ko + c0q * 4);
        CP_A16(base + (uint32_t)(128 * SROW + c1r * SROW + c0q * 4) * 4, Bbase + (size_t)c1r * Kd + ko + c0q * 4);
    };

    float acc[2][8][4];
    #pragma unroll
    for (int mt = 0; mt < 2; mt++)
        #pragma unroll
        for (int nt = 0; nt < 8; nt++)
            #pragma unroll
            for (int q = 0; q < 4; q++) acc[mt][nt][q] = 0.f;

    load_stage(0, 0); CP_COMMIT();
    if (KCz > 1) load_stage(1, 1);
    CP_COMMIT();

    for (int kt = 0; kt < KCz; ++kt) {
        CP_WAIT1();
        __syncthreads();
        const int nx = kt + 2;
        if (nx < KCz) load_stage(nx % 3, nx);
        CP_COMMIT();

        const float* As = sm + (kt % 3) * STAGE_F;
        const float* Bs = As + 128 * SROW;
        #pragma unroll
        for (int kk = 0; kk < 2; kk++) {
            const int kb = kk * 8;
            uint32_t a[2][4], b[8][2];
            #pragma unroll
            for (int mt = 0; mt < 2; mt++) {
                const int r = wrow + mt * 16 + lr;
                a[mt][0] = __float_as_uint(f2tf(As[r * SROW + kb + lc]));
                a[mt][1] = __float_as_uint(f2tf(As[(r + 8) * SROW + kb + lc]));
                a[mt][2] = __float_as_uint(f2tf(As[r * SROW + kb + lc + 4]));
                a[mt][3] = __float_as_uint(f2tf(As[(r + 8) * SROW + kb + lc + 4]));
            }
            #pragma unroll
            for (int nt = 0; nt < 8; nt++) {
                const int n = wcol + nt * 8 + lr;
                b[nt][0] = __float_as_uint(f2tf(Bs[n * SROW + kb + lc]));
                b[nt][1] = __float_as_uint(f2tf(Bs[n * SROW + kb + lc + 4]));
            }
            #pragma unroll
            for (int mt = 0; mt < 2; mt++)
                #pragma unroll
                for (int nt = 0; nt < 8; nt++)
                    mma_tf32(acc[mt][nt], a[mt], b[nt]);
        }
    }

    if (Z == 1) {
        #pragma unroll
        for (int mt = 0; mt < 2; mt++) {
            #pragma unroll
            for (int nt = 0; nt < 8; nt++) {
                const int row0 = m0 + wrow + mt * 16 + lr;
                const int col  = n0 + wcol + nt * 8 + 2 * lc;
                const float b0 = bias[col], b1 = bias[col + 1];
                float v0 = acc[mt][nt][0] + b0, v1 = acc[mt][nt][1] + b1;
                float v2 = acc[mt][nt][2] + b0, v3 = acc[mt][nt][3] + b1;
                if (OUTHALF) {
                    *(__half2*)(Ch + (size_t)row0 * N + col)       = __floats2half2_rn(v0, v1);
                    *(__half2*)(Ch + (size_t)(row0 + 8) * N + col) = __floats2half2_rn(v2, v3);
                } else {
                    *(float2*)(Cf + (size_t)row0 * N + col)       = make_float2(v0, v1);
                    *(float2*)(Cf + (size_t)(row0 + 8) * N + col) = make_float2(v2, v3);
                }
            }
        }
    } else {
        float* P = part + (size_t)blockIdx.z * M * N;
        #pragma unroll
        for (int mt = 0; mt < 2; mt++) {
            #pragma unroll
            for (int nt = 0; nt < 8; nt++) {
                const int row0 = m0 + wrow + mt * 16 + lr;
                const int col  = n0 + wcol + nt * 8 + 2 * lc;
                *(float2*)(P + (size_t)row0 * N + col)       = make_float2(acc[mt][nt][0], acc[mt][nt][1]);
                *(float2*)(P + (size_t)(row0 + 8) * N + col) = make_float2(acc[mt][nt][2], acc[mt][nt][3]);
            }
        }
    }
}

// ============================================================
// split-K merge (elementwise): out = f(sum_z part + bias), opt relu
// ============================================================
template<bool RELU>
__global__ void __launch_bounds__(256) merge_plain(
    const float* __restrict__ part, const float* __restrict__ bias,
    float* __restrict__ out, size_t MN, int N, int Z)
{
    const size_t i = ((size_t)blockIdx.x * 256 + threadIdx.x) * 4;
    float4 s = *(const float4*)(part + i);
    for (int z = 1; z < Z; z++) {
        float4 p = *(const float4*)(part + (size_t)z * MN + i);
        s.x += p.x; s.y += p.y; s.z += p.z; s.w += p.w;
    }
    float4 bb = *(const float4*)(bias + (i % (size_t)N));
    s.x += bb.x; s.y += bb.y; s.z += bb.z; s.w += bb.w;
    if (RELU) {
        s.x = fmaxf(s.x, 0.f); s.y = fmaxf(s.y, 0.f);
        s.z = fmaxf(s.z, 0.f); s.w = fmaxf(s.w, 0.f);
    }
    *(float4*)(out + i) = s;
}

// ============================================================
// merge + residual + LayerNorm (+ optional GAP), single pass:
// partial sums cached in registers, gap via post-sync row reload.
// ============================================================
__global__ void __launch_bounds__(256) merge_ln(
    const float* __restrict__ part, const float* __restrict__ bias,
    const float* __restrict__ res, const float* __restrict__ gamma,
    const float* __restrict__ beta, float* __restrict__ out,
    float* __restrict__ gapOut, int N, int Z, size_t MN)
{
    const int row = blockIdx.x, t = threadIdx.x;
    const size_t base = (size_t)row * N;
    __shared__ float rs[8], rs2[8], smean, sinv;

    float4 val[7];
    float s = 0.f, s2 = 0.f;
    #pragma unroll
    for (int j = 0; j < 7; j++) {
        const int i = (t + j * 256) * 4;
        if (i < N) {
            float4 v = *(const float4*)(part + base + i);
            for (int z = 1; z < Z; z++) {
                float4 p = *(const float4*)(part + (size_t)z * MN + base + i);
                v.x += p.x; v.y += p.y; v.z += p.z; v.w += p.w;
            }
            float4 bb = *(const float4*)(bias + i);
            float4 rr = *(const float4*)(res + base + i);
            v.x += bb.x + rr.x; v.y += bb.y + rr.y;
            v.z += bb.z + rr.z; v.w += bb.w + rr.w;
            val[j] = v;
            s  += v.x + v.y + v.z + v.w;
            s2 += v.x * v.x + v.y * v.y + v.z * v.z + v.w * v.w;
        }
    }
    #pragma unroll
    for (int o = 16; o > 0; o >>= 1) {
        s  += __shfl_xor_sync(~0u, s, o);
        s2 += __shfl_xor_sync(~0u, s2, o);
    }
    if ((t & 31) == 0) { rs[t >> 5] = s; rs2[t >> 5] = s2; }
    __syncthreads();
    if (t == 0) {
        float ts = 0.f, ts2 = 0.f;
        #pragma unroll
        for (int i = 0; i < 8; i++) { ts += rs[i]; ts2 += rs2[i]; }
        float mean = ts / N;
        smean = mean;
        sinv = rsqrtf(ts2 / N - mean * mean + 1e-5f);
    }
    __syncthreads();
    const float mean = smean, inv = sinv;

    #pragma unroll
    for (int j = 0; j < 7; j++) {
        const int i = (t + j * 256) * 4;
        if (i < N) {
            float4 gg = *(const float4*)(gamma + i);
            float4 be = *(const float4*)(beta + i);
            float4 v = val[j];
            v.x = (v.x - mean) * inv * gg.x + be.x;
            v.y = (v.y - mean) * inv * gg.y + be.y;
            v.z = (v.z - mean) * inv * gg.z + be.z;
            v.w = (v.w - mean) * inv * gg.w + be.w;
            *(float4*)(out + base + i) = v;
        }
    }
    if (gapOut) {
        __syncthreads();   // gmem writes by block visible to block after sync
        if (t < Cc) {
            const float* p = out + base + t * 49;
            float a = 0.f;
            #pragma unroll
            for (int q = 0; q < 49; q++) a += p[q];
            gapOut[(size_t)row * Cc + t] = a * (1.f / 49.f);
        }
    }
}

// ============================================================
// dynconv (fp16 dyn weights, vectorized loads) + residual + fused LN2
// ============================================================
__global__ void __launch_bounds__(128) dynconv_ln(
    const float* __restrict__ x, const __half* __restrict__ dyn,
    const float* __restrict__ g2, const float* __restrict__ b2,
    float* __restrict__ out)
{
    const int s = blockIdx.x, t = threadIdx.x;
    __shared__ float sIn[Cc][81];
    __shared__ float rs[4], rs2[4], smean, sinv;
    float* sc = sIn[t];
    #pragma unroll
    for (int i = 0; i < 81; i++) sc[i] = 0.f;
    const float* xp = x + ((size_t)s * Cc + t) * 49;
    #pragma unroll
    for (int y = 0; y < 7; y++)
        #pragma unroll
        for (int xx = 0; xx < 7; xx++)
            sc[(y + 1) * 9 + xx + 1] = xp[y * 7 + xx];
    __syncthreads();

    const int grp = t >> 5;
    const uint4* wb4 = (const uint4*)(dyn + (size_t)s * DYN + (size_t)t * (CPG * 9));
    const float* ib = &sIn[grp * CPG][0];
    float acc[49];
    #pragma unroll
    for (int i = 0; i < 49; i++) acc[i] = 0.f;

    for (int c = 0; c < 4; c++) {          // 8 input channels per chunk
        uint4 w4[9];                        // 72 halves = 8 ic x 9 weights
        #pragma unroll
        for (int j = 0; j < 9; j++) w4[j] = wb4[c * 9 + j];
        const __half* wh = (const __half*)w4;
        #pragma unroll
        for (int i2 = 0; i2 < 8; i2++) {
            const float* in = ib + (c * 8 + i2) * 81;
            const float w0 = __half2float(wh[i2 * 9 + 0]);
            const float w1 = __half2float(wh[i2 * 9 + 1]);
            const float w2 = __half2float(wh[i2 * 9 + 2]);
            const float w3 = __half2float(wh[i2 * 9 + 3]);
            const float w4v = __half2float(wh[i2 * 9 + 4]);
            const float w5 = __half2float(wh[i2 * 9 + 5]);
            const float w6 = __half2float(wh[i2 * 9 + 6]);
            const float w7 = __half2float(wh[i2 * 9 + 7]);
            const float w8 = __half2float(wh[i2 * 9 + 8]);
            #pragma unroll
            for (int y = 0; y < 7; y++) {
                #pragma unroll
                for (int xx = 0; xx < 7; xx++) {
                    float a = acc[y * 7 + xx];
                    a += w0 * in[y * 9 + xx]       + w1 * in[y * 9 + xx + 1]       + w2 * in[y * 9 + xx + 2];
                    a += w3 * in[(y + 1) * 9 + xx] + w4v * in[(y + 1) * 9 + xx + 1] + w5 * in[(y + 1) * 9 + xx + 2];
                    a += w6 * in[(y + 2) * 9 + xx] + w7 * in[(y + 2) * 9 + xx + 1] + w8 * in[(y + 2) * 9 + xx + 2];
                    acc[y * 7 + xx] = a;
                }
            }
        }
    }

    // y = conv + residual, then LN over all Dd elems of the sample
    const float* ms = sIn[t];
    float ss = 0.f, ss2 = 0.f;
    #pragma unroll
    for (int j = 0; j < 49; j++) {
        float yv = acc[j] + ms[(j / 7 + 1) * 9 + (j % 7) + 1];
        acc[j] = yv;
        ss += yv; ss2 += yv * yv;
    }
    #pragma unroll
    for (int o = 16; o > 0; o >>= 1) {
        ss  += __shfl_xor_sync(~0u, ss, o);
        ss2 += __shfl_xor_sync(~0u, ss2, o);
    }
    if ((t & 31) == 0) { rs[t >> 5] = ss; rs2[t >> 5] = ss2; }
    __syncthreads();
    if (t == 0) {
        float ts = rs[0] + rs[1] + rs[2] + rs[3];
        float ts2 = rs2[0] + rs2[1] + rs2[2] + rs2[3];
        float mean = ts / Dd;
        smean = mean;
        sinv = rsqrtf(ts2 / Dd - mean * mean + 1e-5f);
    }
    __syncthreads();
    const float mean = smean, inv = sinv;
    float* op = out + ((size_t)s * Cc + t) * 49;
    const float* gp = g2 + t * 49;
    const float* bp = b2 + t * 49;
    #pragma unroll
    for (int j = 0; j < 49; j++)
        op[j] = (acc[j] - mean) * inv * gp[j] + bp[j];
}

// ============================================================
// cost matrix
// ============================================================
__global__ void __launch_bounds__(256) cost_kernel(
    const float* __restrict__ rb, const float* __restrict__ cb, float* __restrict__ out)
{
    __shared__ float sR[Mb * 4], sC[Mb * 4], sdist[Mb * Mb], rm[8], sMax;
    const int t = threadIdx.x;
    sR[t] = rb[t]; sC[t] = cb[t];
    __syncthreads();
    float lm = 0.f;
    for (int idx = t; idx < Mb * Mb; idx += 256) {
        int i = idx >> 6, j = idx & 63;
        float d = fabsf((sR[i * 4] + sR[i * 4 + 2]) * 0.5f - (sC[j * 4] + sC[j * 4 + 2]) * 0.5f)
                + fabsf((sR[i * 4 + 1] + sR[i * 4 + 3]) * 0.5f - (sC[j * 4 + 1] + sC[j * 4 + 3]) * 0.5f);
        sdist[idx] = d;
        lm = fmaxf(lm, d);
    }
    #pragma unroll
    for (int o = 16; o > 0; o >>= 1) lm = fmaxf(lm, __shfl_xor_sync(~0u, lm, o));
    if ((t & 31) == 0) rm[t >> 5] = lm;
    __syncthreads();
    if (t == 0) {
        float m = 0.f;
        #pragma unroll
        for (int i = 0; i < 8; i++) m = fmaxf(m, rm[i]);
        sMax = fmaxf(m, 1.f);
    }
    __syncthreads();
    const float dmax = sMax;
    for (int idx = t; idx < Mb * Mb; idx += 256) {
        int i = idx >> 6, j = idx & 63;
        float ax0 = sR[i*4], ay0 = sR[i*4+1], ax1 = sR[i*4+2], ay1 = sR[i*4+3];
        float bx0 = sC[j*4], by0 = sC[j*4+1], bx1 = sC[j*4+2], by1 = sC[j*4+3];
        float areaA = (ax1 - ax0) * (ay1 - ay0), areaB = (bx1 - bx0) * (by1 - by0);
        float w = fmaxf(fminf(ax1, bx1) - fmaxf(ax0, bx0), 0.f);
        float h = fmaxf(fminf(ay1, by1) - fmaxf(ay0, by0), 0.f);
        float inter = w * h;
        out[idx] = -inter / (areaA + areaB - inter) + 0.5f * sdist[idx] / dmax;
    }
}

// ============================================================
// host launcher
// ============================================================
extern "C" void kernel_launch(void* const* d_in, const int* in_sizes, int n_in,
                              void* d_out, int out_size)
{
    const float* wf     = (const float*)d_in[0];
    const float* rf     = (const float*)d_in[1];
    const float* refb   = (const float*)d_in[2];
    const float* curb   = (const float*)d_in[3];
    // d_in[4..7] dead (softmax over one key == 1 -> attn == v)
    const float* wv     = (const float*)d_in[8];
    const float* bv     = (const float*)d_in[9];
    const float* wo     = (const float*)d_in[10];
    const float* bo     = (const float*)d_in[11];
    const float* g1     = (const float*)d_in[12];
    const float* b1     = (const float*)d_in[13];
    const float* wgen_w = (const float*)d_in[14];
    const float* wgen_b = (const float*)d_in[15];
    const float* g2     = (const float*)d_in[16];
    const float* b2     = (const float*)d_in[17];
    const float* wf1    = (const float*)d_in[18];
    const float* bf1    = (const float*)d_in[19];
    const float* wf2    = (const float*)d_in[20];
    const float* bf2    = (const float*)d_in[21];
    const float* g3     = (const float*)d_in[22];
    const float* b3     = (const float*)d_in[23];
    float* out = (float*)d_out;

    float *v, *x, *flat, *gap, *h, *part;
    __half* dynh;
    cudaGetSymbolAddress((void**)&v, g_v);       cudaGetSymbolAddress((void**)&x, g_x);
    cudaGetSymbolAddress((void**)&flat, g_flat); cudaGetSymbolAddress((void**)&gap, g_gap);
    cudaGetSymbolAddress((void**)&dynh, g_dynh); cudaGetSymbolAddress((void**)&h, g_h);
    cudaGetSymbolAddress((void**)&part, g_part);

    cudaFuncSetAttribute(gemm_t<false>, cudaFuncAttributeMaxDynamicSharedMemorySize, GEMM_SMEM);
    cudaFuncSetAttribute(gemm_t<true>,  cudaFuncAttributeMaxDynamicSharedMemorySize, GEMM_SMEM);

    const size_t MN1 = (size_t)Kn * Dd;     // 6.42M
    const size_t MNF = (size_t)Kn * FFNn;   // 1.05M

    // 1. v = rf @ wv^T + bv                        (Z=3: 1176 CTAs ~ 4 full waves)
    gemm_t<false><<<dim3(8, 49, 3), 256, GEMM_SMEM>>>(rf, wv, bv, nullptr, nullptr, part, Dd, Dd, 392);
    merge_plain<false><<<(int)(MN1 / 1024), 256>>>(part, bv, v, MN1, Dd, 3);
    // 2. x = LN1(v @ wo^T + bo + wf), gap           (Z=3, fused merge+LN+GAP)
    gemm_t<false><<<dim3(8, 49, 3), 256, GEMM_SMEM>>>(v, wo, bo, nullptr, nullptr, part, Dd, Dd, 392);
    merge_ln<<<Kn, 256>>>(part, bo, wf, g1, b1, x, gap, Dd, 3, MN1);
    // 3. dyn(half) = gap @ wgen^T + wgen_b          (Z=1, fp16 out, 2304 CTAs)
    gemm_t<true><<<dim3(8, 288, 1), 256, GEMM_SMEM>>>(gap, wgen_w, wgen_b, nullptr, dynh, part, DYN, Cc, 8);
    // 4. flat = LN2(dynconv(x) + x)
    dynconv_ln<<<Kn, 128>>>(x, dynh, g2, b2, flat);
    // 5. h = relu(flat @ wf1^T + bf1)               (Z=4)
    gemm_t<false><<<dim3(8, 8, 4), 256, GEMM_SMEM>>>(flat, wf1, bf1, nullptr, nullptr, part, FFNn, Dd, 392);
    merge_plain<true><<<(int)(MNF / 1024), 256>>>(part, bf1, h, MNF, FFNn, 4);
    // 6. out = LN3(h @ wf2^T + bf2 + flat)          (Z=3, fused merge+LN)
    gemm_t<false><<<dim3(8, 49, 3), 256, GEMM_SMEM>>>(h, wf2, bf2, nullptr, nullptr, part, Dd, FFNn, 64);
    merge_ln<<<Kn, 256>>>(part, bf2, flat, g3, b3, out, nullptr, Dd, 3, MN1);
    // 7. cost matrix
    cost_kernel<<<1, 256>>>(refb, curb, out + (size_t)Kn * Dd);
}

// round 16
// speedup vs baseline: 1.2808x; 1.0232x over previous
#include <cuda_runtime.h>
#include <cuda_fp16.h>
#include <cstdint>
#include <cstddef>

constexpr int Kn = 1024, Cc = 128, Dd = 6272, FFNn = 1024, CPG = 32, DYN = 36864, Mb = 64;

// ---------------- scratch ----------------
__device__ __align__(128) float  g_v   [(size_t)Kn * Dd];
__device__ __align__(128) float  g_x   [(size_t)Kn * Dd];
__device__ __align__(128) float  g_flat[(size_t)Kn * Dd];
__device__ __align__(128) float  g_gap [(size_t)Kn * Cc];
__device__ __align__(128) __half g_dynh[(size_t)Kn * DYN];
__device__ __align__(128) float  g_h   [(size_t)Kn * FFNn];
__device__ __align__(128) __half g_part[(size_t)4 * Kn * Dd];  // fp16 split-K partials (Z<=4)

// ---------------- PTX helpers ----------------
__device__ __forceinline__ float f2tf(float x) {
    uint32_t r;
    asm("cvt.rna.tf32.f32 %0, %1;" : "=r"(r) : "f"(x));
    return __uint_as_float(r);
}
__device__ __forceinline__ void mma_tf32(float* c, const uint32_t* a, const uint32_t* b) {
    asm volatile(
        "mma.sync.aligned.m16n8k8.row.col.f32.tf32.tf32.f32 "
        "{%0,%1,%2,%3}, {%4,%5,%6,%7}, {%8,%9}, {%0,%1,%2,%3};"
        : "+f"(c[0]), "+f"(c[1]), "+f"(c[2]), "+f"(c[3])
        : "r"(a[0]), "r"(a[1]), "r"(a[2]), "r"(a[3]), "r"(b[0]), "r"(b[1]));
}
#define CP_A16(dst, src) \
    asm volatile("cp.async.ca.shared.global [%0], [%1], 16;" :: "r"(dst), "l"(src) : "memory")
#define CP_COMMIT() asm volatile("cp.async.commit_group;" ::: "memory")
#define CP_WAIT1()  asm volatile("cp.async.wait_group 1;" ::: "memory")

// ============================================================
// tf32 GEMM: 128x128 block, 8 warps (32x64), occ 2, 3-stage cp.async,
// in-loop cvt. gridDim.z = Z-way split-K (variable per-z KC).
// Z==1 -> C (+bias, fp32 or fp16 out), Z>1 -> fp16 partials.
// ============================================================
constexpr int SROW = 20;
constexpr int STAGE_F = 2 * 128 * SROW;     // 5120 floats
constexpr int GEMM_SMEM = 3 * STAGE_F * 4;  // 61440 B

template<bool OUTHALF>
__global__ void __launch_bounds__(256, 2) gemm_t(
    const float* __restrict__ A, const float* __restrict__ B,
    const float* __restrict__ bias, float* __restrict__ Cf,
    __half* __restrict__ Ch, __half* __restrict__ part,
    int N, int Kd, int KC)
{
    extern __shared__ float sm[];
    const int tid = threadIdx.x;
    const int wid = tid >> 5, lane = tid & 31;
    const int lr = lane >> 2, lc = lane & 3;
    const int m0 = blockIdx.x * 128, n0 = blockIdx.y * 128;
    const int wrow = (wid >> 1) * 32, wcol = (wid & 1) * 64;
    const int Z = gridDim.z;
    const int KCn = (KC + Z - 1) / Z;
    const int kc0 = blockIdx.z * KCn;
    const int KCz = min(KCn, KC - kc0);
    const int M = gridDim.x * 128;

    const uint32_t smem_base = (uint32_t)__cvta_generic_to_shared(sm);
    const int c0r = tid >> 2, c0q = tid & 3;
    const int c1r = (tid + 256) >> 2;

    const float* Abase = A + (size_t)m0 * Kd;
    const float* Bbase = B + (size_t)n0 * Kd;

    auto load_stage = [&](int s, int kt) {
        const uint32_t base = smem_base + (uint32_t)s * (STAGE_F * 4);
        const int ko = (kc0 + kt) * 16;
        CP_A16(base + (uint32_t)(c0r * SROW + c0q * 4) * 4,              Abase + (size_t)c0r * Kd + ko + c0q * 4);
        CP_A16(base + (uint32_t)(c1r * SROW + c0q * 4) * 4,              Abase + (size_t)c1r * Kd + ko + c0q * 4);
        CP_A16(base + (uint32_t)(128 * SROW + c0r * SROW + c0q * 4) * 4, Bbase + (size_t)c0r * Kd + ko + c0q * 4);
        CP_A16(base + (uint32_t)(128 * SROW + c1r * SROW + c0q * 4) * 4, Bbase + (size_t)c1r * Kd + ko + c0q * 4);
    };

    float acc[2][8][4];
    #pragma unroll
    for (int mt = 0; mt < 2; mt++)
        #pragma unroll
        for (int nt = 0; nt < 8; nt++)
            #pragma unroll
            for (int q = 0; q < 4; q++) acc[mt][nt][q] = 0.f;

    load_stage(0, 0); CP_COMMIT();
    if (KCz > 1) load_stage(1, 1);
    CP_COMMIT();

    for (int kt = 0; kt < KCz; ++kt) {
        CP_WAIT1();
        __syncthreads();
        const int nx = kt + 2;
        if (nx < KCz) load_stage(nx % 3, nx);
        CP_COMMIT();

        const float* As = sm + (kt % 3) * STAGE_F;
        const float* Bs = As + 128 * SROW;
        #pragma unroll
        for (int kk = 0; kk < 2; kk++) {
            const int kb = kk * 8;
            uint32_t a[2][4], b[8][2];
            #pragma unroll
            for (int mt = 0; mt < 2; mt++) {
                const int r = wrow + mt * 16 + lr;
                a[mt][0] = __float_as_uint(f2tf(As[r * SROW + kb + lc]));
                a[mt][1] = __float_as_uint(f2tf(As[(r + 8) * SROW + kb + lc]));
                a[mt][2] = __float_as_uint(f2tf(As[r * SROW + kb + lc + 4]));
                a[mt][3] = __float_as_uint(f2tf(As[(r + 8) * SROW + kb + lc + 4]));
            }
            #pragma unroll
            for (int nt = 0; nt < 8; nt++) {
                const int n = wcol + nt * 8 + lr;
                b[nt][0] = __float_as_uint(f2tf(Bs[n * SROW + kb + lc]));
                b[nt][1] = __float_as_uint(f2tf(Bs[n * SROW + kb + lc + 4]));
            }
            #pragma unroll
            for (int mt = 0; mt < 2; mt++)
                #pragma unroll
                for (int nt = 0; nt < 8; nt++)
                    mma_tf32(acc[mt][nt], a[mt], b[nt]);
        }
    }

    if (Z == 1) {
        #pragma unroll
        for (int mt = 0; mt < 2; mt++) {
            #pragma unroll
            for (int nt = 0; nt < 8; nt++) {
                const int row0 = m0 + wrow + mt * 16 + lr;
                const int col  = n0 + wcol + nt * 8 + 2 * lc;
                const float b0 = bias[col], b1 = bias[col + 1];
                float v0 = acc[mt][nt][0] + b0, v1 = acc[mt][nt][1] + b1;
                float v2 = acc[mt][nt][2] + b0, v3 = acc[mt][nt][3] + b1;
                if (OUTHALF) {
                    *(__half2*)(Ch + (size_t)row0 * N + col)       = __floats2half2_rn(v0, v1);
                    *(__half2*)(Ch + (size_t)(row0 + 8) * N + col) = __floats2half2_rn(v2, v3);
                } else {
                    *(float2*)(Cf + (size_t)row0 * N + col)       = make_float2(v0, v1);
                    *(float2*)(Cf + (size_t)(row0 + 8) * N + col) = make_float2(v2, v3);
                }
            }
        }
    } else {
        __half* P = part + (size_t)blockIdx.z * M * N;
        #pragma unroll
        for (int mt = 0; mt < 2; mt++) {
            #pragma unroll
            for (int nt = 0; nt < 8; nt++) {
                const int row0 = m0 + wrow + mt * 16 + lr;
                const int col  = n0 + wcol + nt * 8 + 2 * lc;
                *(__half2*)(P + (size_t)row0 * N + col)       = __floats2half2_rn(acc[mt][nt][0], acc[mt][nt][1]);
                *(__half2*)(P + (size_t)(row0 + 8) * N + col) = __floats2half2_rn(acc[mt][nt][2], acc[mt][nt][3]);
            }
        }
    }
}

// ============================================================
// split-K merge (fp16 partials): out = f(sum_z part + bias), opt relu
// ============================================================
template<bool RELU>
__global__ void __launch_bounds__(256) merge_plain(
    const __half* __restrict__ part, const float* __restrict__ bias,
    float* __restrict__ out, size_t MN, int N, int Z)
{
    const size_t i = ((size_t)blockIdx.x * 256 + threadIdx.x) * 4;
    const __half2* p0 = (const __half2*)(part + i);
    float2 a = __half22float2(p0[0]), b = __half22float2(p0[1]);
    float4 s = make_float4(a.x, a.y, b.x, b.y);
    for (int z = 1; z < Z; z++) {
        const __half2* pz = (const __half2*)(part + (size_t)z * MN + i);
        float2 c = __half22float2(pz[0]), d = __half22float2(pz[1]);
        s.x += c.x; s.y += c.y; s.z += d.x; s.w += d.y;
    }
    float4 bb = *(const float4*)(bias + (i % (size_t)N));
    s.x += bb.x; s.y += bb.y; s.z += bb.z; s.w += bb.w;
    if (RELU) {
        s.x = fmaxf(s.x, 0.f); s.y = fmaxf(s.y, 0.f);
        s.z = fmaxf(s.z, 0.f); s.w = fmaxf(s.w, 0.f);
    }
    *(float4*)(out + i) = s;
}

// ============================================================
// merge(fp16 partials) + residual + LN (+ optional GAP), 512 threads,
// single pass: values cached in registers.
// ============================================================
__global__ void __launch_bounds__(512) merge_ln(
    const __half* __restrict__ part, const float* __restrict__ bias,
    const float* __restrict__ res, const float* __restrict__ gamma,
    const float* __restrict__ beta, float* __restrict__ out,
    float* __restrict__ gapOut, int N, int Z, size_t MN)
{
    const int row = blockIdx.x, t = threadIdx.x;
    const size_t base = (size_t)row * N;
    __shared__ float rs[16], rs2[16], smean, sinv;

    float4 val[4];
    float s = 0.f, s2 = 0.f;
    #pragma unroll
    for (int j = 0; j < 4; j++) {
        const int i = (t + j * 512) * 4;
        if (i < N) {
            const __half2* p0 = (const __half2*)(part + base + i);
            float2 a = __half22float2(p0[0]), b = __half22float2(p0[1]);
            float4 v = make_float4(a.x, a.y, b.x, b.y);
            for (int z = 1; z < Z; z++) {
                const __half2* pz = (const __half2*)(part + (size_t)z * MN + base + i);
                float2 c = __half22float2(pz[0]), d = __half22float2(pz[1]);
                v.x += c.x; v.y += c.y; v.z += d.x; v.w += d.y;
            }
            float4 bb = *(const float4*)(bias + i);
            float4 rr = *(const float4*)(res + base + i);
            v.x += bb.x + rr.x; v.y += bb.y + rr.y;
            v.z += bb.z + rr.z; v.w += bb.w + rr.w;
            val[j] = v;
            s  += v.x + v.y + v.z + v.w;
            s2 += v.x * v.x + v.y * v.y + v.z * v.z + v.w * v.w;
        }
    }
    #pragma unroll
    for (int o = 16; o > 0; o >>= 1) {
        s  += __shfl_xor_sync(~0u, s, o);
        s2 += __shfl_xor_sync(~0u, s2, o);
    }
    if ((t & 31) == 0) { rs[t >> 5] = s; rs2[t >> 5] = s2; }
    __syncthreads();
    if (t == 0) {
        float ts = 0.f, ts2 = 0.f;
        #pragma unroll
        for (int i = 0; i < 16; i++) { ts += rs[i]; ts2 += rs2[i]; }
        float mean = ts / N;
        smean = mean;
        sinv = rsqrtf(ts2 / N - mean * mean + 1e-5f);
    }
    __syncthreads();
    const float mean = smean, inv = sinv;

    #pragma unroll
    for (int j = 0; j < 4; j++) {
        const int i = (t + j * 512) * 4;
        if (i < N) {
            float4 gg = *(const float4*)(gamma + i);
            float4 be = *(const float4*)(beta + i);
            float4 v = val[j];
            v.x = (v.x - mean) * inv * gg.x + be.x;
            v.y = (v.y - mean) * inv * gg.y + be.y;
            v.z = (v.z - mean) * inv * gg.z + be.z;
            v.w = (v.w - mean) * inv * gg.w + be.w;
            *(float4*)(out + base + i) = v;
        }
    }
    if (gapOut) {
        __syncthreads();   // this block's gmem writes visible to this block
        if (t < Cc) {
            const float* p = out + base + t * 49;
            float a = 0.f;
            #pragma unroll
            for (int q = 0; q < 49; q++) a += p[q];
            gapOut[(size_t)row * Cc + t] = a * (1.f / 49.f);
        }
    }
}

// ============================================================
// dynconv (fp16 dyn weights, vectorized loads) + residual + fused LN2
// ============================================================
__global__ void __launch_bounds__(128) dynconv_ln(
    const float* __restrict__ x, const __half* __restrict__ dyn,
    const float* __restrict__ g2, const float* __restrict__ b2,
    float* __restrict__ out)
{
    const int s = blockIdx.x, t = threadIdx.x;
    __shared__ float sIn[Cc][81];
    __shared__ float rs[4], rs2[4], smean, sinv;
    float* sc = sIn[t];
    #pragma unroll
    for (int i = 0; i < 81; i++) sc[i] = 0.f;
    const float* xp = x + ((size_t)s * Cc + t) * 49;
    #pragma unroll
    for (int y = 0; y < 7; y++)
        #pragma unroll
        for (int xx = 0; xx < 7; xx++)
            sc[(y + 1) * 9 + xx + 1] = xp[y * 7 + xx];
    __syncthreads();

    const int grp = t >> 5;
    const uint4* wb4 = (const uint4*)(dyn + (size_t)s * DYN + (size_t)t * (CPG * 9));
    const float* ib = &sIn[grp * CPG][0];
    float acc[49];
    #pragma unroll
    for (int i = 0; i < 49; i++) acc[i] = 0.f;

    for (int c = 0; c < 4; c++) {          // 8 input channels per chunk
        uint4 w4[9];
        #pragma unroll
        for (int j = 0; j < 9; j++) w4[j] = wb4[c * 9 + j];
        const __half* wh = (const __half*)w4;
        #pragma unroll
        for (int i2 = 0; i2 < 8; i2++) {
            const float* in = ib + (c * 8 + i2) * 81;
            const float w0 = __half2float(wh[i2 * 9 + 0]);
            const float w1 = __half2float(wh[i2 * 9 + 1]);
            const float w2 = __half2float(wh[i2 * 9 + 2]);
            const float w3 = __half2float(wh[i2 * 9 + 3]);
            const float w4v = __half2float(wh[i2 * 9 + 4]);
            const float w5 = __half2float(wh[i2 * 9 + 5]);
            const float w6 = __half2float(wh[i2 * 9 + 6]);
            const float w7 = __half2float(wh[i2 * 9 + 7]);
            const float w8 = __half2float(wh[i2 * 9 + 8]);
            #pragma unroll
            for (int y = 0; y < 7; y++) {
                #pragma unroll
                for (int xx = 0; xx < 7; xx++) {
                    float a = acc[y * 7 + xx];
                    a += w0 * in[y * 9 + xx]       + w1 * in[y * 9 + xx + 1]       + w2 * in[y * 9 + xx + 2];
                    a += w3 * in[(y + 1) * 9 + xx] + w4v * in[(y + 1) * 9 + xx + 1] + w5 * in[(y + 1) * 9 + xx + 2];
                    a += w6 * in[(y + 2) * 9 + xx] + w7 * in[(y + 2) * 9 + xx + 1] + w8 * in[(y + 2) * 9 + xx + 2];
                    acc[y * 7 + xx] = a;
                }
            }
        }
    }

    const float* ms = sIn[t];
    float ss = 0.f, ss2 = 0.f;
    #pragma unroll
    for (int j = 0; j < 49; j++) {
        float yv = acc[j] + ms[(j / 7 + 1) * 9 + (j % 7) + 1];
        acc[j] = yv;
        ss += yv; ss2 += yv * yv;
    }
    #pragma unroll
    for (int o = 16; o > 0; o >>= 1) {
        ss  += __shfl_xor_sync(~0u, ss, o);
        ss2 += __shfl_xor_sync(~0u, ss2, o);
    }
    if ((t & 31) == 0) { rs[t >> 5] = ss; rs2[t >> 5] = ss2; }
    __syncthreads();
    if (t == 0) {
        float ts = rs[0] + rs[1] + rs[2] + rs[3];
        float ts2 = rs2[0] + rs2[1] + rs2[2] + rs2[3];
        float mean = ts / Dd;
        smean = mean;
        sinv = rsqrtf(ts2 / Dd - mean * mean + 1e-5f);
    }
    __syncthreads();
    const float mean = smean, inv = sinv;
    float* op = out + ((size_t)s * Cc + t) * 49;
    const float* gp = g2 + t * 49;
    const float* bp = b2 + t * 49;
    #pragma unroll
    for (int j = 0; j < 49; j++)
        op[j] = (acc[j] - mean) * inv * gp[j] + bp[j];
}

// ============================================================
// cost matrix
// ============================================================
__global__ void __launch_bounds__(256) cost_kernel(
    const float* __restrict__ rb, const float* __restrict__ cb, float* __restrict__ out)
{
    __shared__ float sR[Mb * 4], sC[Mb * 4], sdist[Mb * Mb], rm[8], sMax;
    const int t = threadIdx.x;
    sR[t] = rb[t]; sC[t] = cb[t];
    __syncthreads();
    float lm = 0.f;
    for (int idx = t; idx < Mb * Mb; idx += 256) {
        int i = idx >> 6, j = idx & 63;
        float d = fabsf((sR[i * 4] + sR[i * 4 + 2]) * 0.5f - (sC[j * 4] + sC[j * 4 + 2]) * 0.5f)
                + fabsf((sR[i * 4 + 1] + sR[i * 4 + 3]) * 0.5f - (sC[j * 4 + 1] + sC[j * 4 + 3]) * 0.5f);
        sdist[idx] = d;
        lm = fmaxf(lm, d);
    }
    #pragma unroll
    for (int o = 16; o > 0; o >>= 1) lm = fmaxf(lm, __shfl_xor_sync(~0u, lm, o));
    if ((t & 31) == 0) rm[t >> 5] = lm;
    __syncthreads();
    if (t == 0) {
        float m = 0.f;
        #pragma unroll
        for (int i = 0; i < 8; i++) m = fmaxf(m, rm[i]);
        sMax = fmaxf(m, 1.f);
    }
    __syncthreads();
    const float dmax = sMax;
    for (int idx = t; idx < Mb * Mb; idx += 256) {
        int i = idx >> 6, j = idx & 63;
        float ax0 = sR[i*4], ay0 = sR[i*4+1], ax1 = sR[i*4+2], ay1 = sR[i*4+3];
        float bx0 = sC[j*4], by0 = sC[j*4+1], bx1 = sC[j*4+2], by1 = sC[j*4+3];
        float areaA = (ax1 - ax0) * (ay1 - ay0), areaB = (bx1 - bx0) * (by1 - by0);
        float w = fmaxf(fminf(ax1, bx1) - fmaxf(ax0, bx0), 0.f);
        float h = fmaxf(fminf(ay1, by1) - fmaxf(ay0, by0), 0.f);
        float inter = w * h;
        out[idx] = -inter / (areaA + areaB - inter) + 0.5f * sdist[idx] / dmax;
    }
}

// ============================================================
// host launcher
// ============================================================
extern "C" void kernel_launch(void* const* d_in, const int* in_sizes, int n_in,
                              void* d_out, int out_size)
{
    const float* wf     = (const float*)d_in[0];
    const float* rf     = (const float*)d_in[1];
    const float* refb   = (const float*)d_in[2];
    const float* curb   = (const float*)d_in[3];
    // d_in[4..7] dead (softmax over one key == 1 -> attn == v)
    const float* wv     = (const float*)d_in[8];
    const float* bv     = (const float*)d_in[9];
    const float* wo     = (const float*)d_in[10];
    const float* bo     = (const float*)d_in[11];
    const float* g1     = (const float*)d_in[12];
    const float* b1     = (const float*)d_in[13];
    const float* wgen_w = (const float*)d_in[14];
    const float* wgen_b = (const float*)d_in[15];
    const float* g2     = (const float*)d_in[16];
    const float* b2     = (const float*)d_in[17];
    const float* wf1    = (const float*)d_in[18];
    const float* bf1    = (const float*)d_in[19];
    const float* wf2    = (const float*)d_in[20];
    const float* bf2    = (const float*)d_in[21];
    const float* g3     = (const float*)d_in[22];
    const float* b3     = (const float*)d_in[23];
    float* out = (float*)d_out;

    float *v, *x, *flat, *gap, *h;
    __half *dynh, *part;
    cudaGetSymbolAddress((void**)&v, g_v);       cudaGetSymbolAddress((void**)&x, g_x);
    cudaGetSymbolAddress((void**)&flat, g_flat); cudaGetSymbolAddress((void**)&gap, g_gap);
    cudaGetSymbolAddress((void**)&dynh, g_dynh); cudaGetSymbolAddress((void**)&h, g_h);
    cudaGetSymbolAddress((void**)&part, g_part);

    cudaFuncSetAttribute(gemm_t<false>, cudaFuncAttributeMaxDynamicSharedMemorySize, GEMM_SMEM);
    cudaFuncSetAttribute(gemm_t<true>,  cudaFuncAttributeMaxDynamicSharedMemorySize, GEMM_SMEM);

    const size_t MN1 = (size_t)Kn * Dd;     // 6.42M
    const size_t MNF = (size_t)Kn * FFNn;   // 1.05M

    // 1. v = rf @ wv^T + bv                        (Z=3: 1176 CTAs ~ 4 full waves)
    gemm_t<false><<<dim3(8, 49, 3), 256, GEMM_SMEM>>>(rf, wv, bv, nullptr, nullptr, part, Dd, Dd, 392);
    merge_plain<false><<<(int)(MN1 / 1024), 256>>>(part, bv, v, MN1, Dd, 3);
    // 2. x = LN1(v @ wo^T + bo + wf), gap           (Z=3, fused merge+LN+GAP)
    gemm_t<false><<<dim3(8, 49, 3), 256, GEMM_SMEM>>>(v, wo, bo, nullptr, nullptr, part, Dd, Dd, 392);
    merge_ln<<<Kn, 512>>>(part, bo, wf, g1, b1, x, gap, Dd, 3, MN1);
    // 3. dyn(half) = gap @ wgen^T + wgen_b          (Z=1, fp16 out)
    gemm_t<true><<<dim3(8, 288, 1), 256, GEMM_SMEM>>>(gap, wgen_w, wgen_b, nullptr, dynh, part, DYN, Cc, 8);
    // 4. flat = LN2(dynconv(x) + x)
    dynconv_ln<<<Kn, 128>>>(x, dynh, g2, b2, flat);
    // 5. h = relu(flat @ wf1^T + bf1)               (Z=4)
    gemm_t<false><<<dim3(8, 8, 4), 256, GEMM_SMEM>>>(flat, wf1, bf1, nullptr, nullptr, part, FFNn, Dd, 392);
    merge_plain<true><<<(int)(MNF / 1024), 256>>>(part, bf1, h, MNF, FFNn, 4);
    // 6. out = LN3(h @ wf2^T + bf2 + flat)          (Z=3, fused merge+LN)
    gemm_t<false><<<dim3(8, 49, 3), 256, GEMM_SMEM>>>(h, wf2, bf2, nullptr, nullptr, part, Dd, FFNn, 64);
    merge_ln<<<Kn, 512>>>(part, bf2, flat, g3, b3, out, nullptr, Dd, 3, MN1);
    // 7. cost matrix
    cost_kernel<<<1, 256>>>(refb, curb, out + (size_t)Kn * Dd);
}